// round 7
// baseline (speedup 1.0000x reference)
#include <cuda_runtime.h>
#include <cuda_fp16.h>
#include <math.h>
#include <stdint.h>

#define NB   4096
#define NE   16
#define DI   1024
#define DH   2048
#define DOUT 1024
#define NSLOT (NB * 2)
#define MAXT 80            // max 128-row m-tiles across experts (<=79, pad 80)
#define W1CB 512           // w1 converter blocks (in gate grid, 128 thr)
#define XCB  64            // x converter blocks (in scatter grid, 256 thr)
#define W2CY 8             // extra grid.y rows of w2 converters in GEMM1

// ---------------- scratch ----------------------------------------------------
__device__ __half g_xh[(size_t)NB * DI];            // fp16 x
__device__ __half g_w1h[(size_t)NE * DH * DI];      // fp16 w1
__device__ __half g_w2h[(size_t)NE * DOUT * DH];    // fp16 w2
__device__ __half g_h[(size_t)NSLOT * DH];          // fp16 hidden
__device__ float  g_contrib[(size_t)NSLOT * DOUT];
__device__ int    g_perm[NSLOT];
__device__ int    g_inv[NSLOT];
__device__ int    g_counts[NE];
__device__ int    g_cursor[NE];
__device__ int    g_off[NE + 1];
__device__ int    g_tidx[NB * 2];
__device__ float  g_tw[NB * 2];
__device__ int    g_tile_e[MAXT];
__device__ int    g_tile_m[MAXT];

// ---------------- helpers ----------------------------------------------------
__device__ __forceinline__ void ldsm4(uint32_t addr, uint32_t* a) {
    asm volatile("ldmatrix.sync.aligned.m8n8.x4.shared.b16 {%0,%1,%2,%3}, [%4];"
                 : "=r"(a[0]), "=r"(a[1]), "=r"(a[2]), "=r"(a[3]) : "r"(addr));
}
__device__ __forceinline__ void mma_f16(float* d, const uint32_t* a, const uint32_t* b) {
    asm volatile(
        "mma.sync.aligned.m16n8k16.row.col.f32.f16.f16.f32 "
        "{%0,%1,%2,%3}, {%4,%5,%6,%7}, {%8,%9}, {%0,%1,%2,%3};"
        : "+f"(d[0]), "+f"(d[1]), "+f"(d[2]), "+f"(d[3])
        : "r"(a[0]), "r"(a[1]), "r"(a[2]), "r"(a[3]), "r"(b[0]), "r"(b[1]));
}
__device__ __forceinline__ uint32_t h2bits(__half2 h) {
    return *reinterpret_cast<uint32_t*>(&h);
}
__device__ __forceinline__ uint2 cvt2h(float4 v) {
    uint2 u;
    u.x = h2bits(__floats2half2_rn(v.x, v.y));
    u.y = h2bits(__floats2half2_rn(v.z, v.w));
    return u;
}
__device__ __forceinline__ void cp16(uint32_t dst, const void* src) {
    asm volatile("cp.async.ca.shared.global [%0], [%1], 16;" :: "r"(dst), "l"(src));
}
__device__ __forceinline__ void cp_commit() {
    asm volatile("cp.async.commit_group;" ::: "memory");
}
template <int N>
__device__ __forceinline__ void cp_wait() {
    asm volatile("cp.async.wait_group %0;" :: "n"(N) : "memory");
}

// ---------------- gate (fp32 exact) + w1 converter ----------------------------
__global__ __launch_bounds__(128) void gate_kernel(const float* __restrict__ x,
                                                   const float* __restrict__ gw,
                                                   const float4* __restrict__ w1f4) {
    if (blockIdx.x >= NB / 4) {                      // w1 fp32 -> fp16 converter
        int c = blockIdx.x - NB / 4;
        size_t base = (size_t)c * 128 + threadIdx.x;
        const size_t STRIDE = (size_t)W1CB * 128;
        uint2* dst = (uint2*)g_w1h;
        #pragma unroll 8
        for (int i = 0; i < (NE * DH * DI / 4) / (W1CB * 128); ++i)
            dst[base + i * STRIDE] = cvt2h(w1f4[base + i * STRIDE]);
        return;
    }

    __shared__ float xs[4][DI];
    __shared__ float sc[4][NE];
    int t0 = blockIdx.x * 4;

    const float4* xsrc = (const float4*)(x + (size_t)t0 * DI);
    float4* xd = (float4*)&xs[0][0];
    #pragma unroll 4
    for (int i = threadIdx.x; i < 4 * DI / 4; i += 128) xd[i] = xsrc[i];
    __syncthreads();

    int warp = threadIdx.x >> 5, lane = threadIdx.x & 31;
    for (int e = warp * 4; e < warp * 4 + 4; ++e) {
        float s0 = 0.f, s1 = 0.f, s2 = 0.f, s3 = 0.f;
        for (int i = lane; i < DI; i += 32) {
            float g = gw[e * DI + i];
            s0 += xs[0][i] * g; s1 += xs[1][i] * g;
            s2 += xs[2][i] * g; s3 += xs[3][i] * g;
        }
        #pragma unroll
        for (int o = 16; o > 0; o >>= 1) {
            s0 += __shfl_xor_sync(0xffffffffu, s0, o);
            s1 += __shfl_xor_sync(0xffffffffu, s1, o);
            s2 += __shfl_xor_sync(0xffffffffu, s2, o);
            s3 += __shfl_xor_sync(0xffffffffu, s3, o);
        }
        if (lane == 0) { sc[0][e] = s0; sc[1][e] = s1; sc[2][e] = s2; sc[3][e] = s3; }
    }
    __syncthreads();

    if (threadIdx.x < 4) {
        int tt = threadIdx.x;
        int tok = t0 + tt;
        float bv = -1e30f; int bi = 0;
        #pragma unroll
        for (int e = 0; e < NE; ++e) {
            float v = sc[tt][e];
            if (v > bv) { bv = v; bi = e; }
        }
        float bv2 = -1e30f; int bi2 = 0;
        #pragma unroll
        for (int e = 0; e < NE; ++e) {
            if (e == bi) continue;
            float v = sc[tt][e];
            if (v > bv2) { bv2 = v; bi2 = e; }
        }
        float e2 = expf(bv2 - bv);
        float inv = 1.0f / (1.0f + e2);
        g_tidx[tok * 2 + 0] = bi;  g_tw[tok * 2 + 0] = inv;
        g_tidx[tok * 2 + 1] = bi2; g_tw[tok * 2 + 1] = e2 * inv;
        atomicAdd(&g_counts[bi], 1);
        atomicAdd(&g_counts[bi2], 1);
    }
}

// ---------------- prefix + exact tile table ----------------------------------
__global__ void prefix_kernel() {
    if (threadIdx.x == 0) {
        int s = 0;
        #pragma unroll
        for (int e = 0; e < NE; ++e) { g_off[e] = s; s += g_counts[e]; }
        g_off[NE] = s;
        int nt = 0;
        for (int e = 0; e < NE; ++e)
            for (int m = g_off[e]; m < g_off[e + 1]; m += 128) {
                g_tile_e[nt] = e; g_tile_m[nt] = m; ++nt;
            }
        for (; nt < MAXT; ++nt) g_tile_e[nt] = -1;
    }
}

// ---------------- scatter + x converter ---------------------------------------
__global__ __launch_bounds__(256) void scatter_kernel(const float4* __restrict__ xf4) {
    if (blockIdx.x >= NB / 256) {                    // x fp32 -> fp16 converter
        int c = blockIdx.x - NB / 256;
        size_t base = (size_t)c * 256 + threadIdx.x;
        const size_t STRIDE = (size_t)XCB * 256;
        uint2* dst = (uint2*)g_xh;
        #pragma unroll 8
        for (int i = 0; i < (NB * DI / 4) / (XCB * 256); ++i)
            dst[base + i * STRIDE] = cvt2h(xf4[base + i * STRIDE]);
        return;
    }
    __shared__ int lcnt[NE];
    __shared__ int lbase[NE];
    int tid = threadIdx.x;
    int tok = blockIdx.x * 256 + tid;
    if (tid < NE) lcnt[tid] = 0;
    __syncthreads();
    int e0 = g_tidx[tok * 2 + 0], e1 = g_tidx[tok * 2 + 1];
    int r0 = atomicAdd(&lcnt[e0], 1);
    int r1 = atomicAdd(&lcnt[e1], 1);
    __syncthreads();
    if (tid < NE) lbase[tid] = atomicAdd(&g_cursor[tid], lcnt[tid]);
    __syncthreads();
    int p0 = g_off[e0] + lbase[e0] + r0;
    int p1 = g_off[e1] + lbase[e1] + r1;
    g_perm[p0] = tok * 2 + 0;  g_inv[tok * 2 + 0] = p0;
    g_perm[p1] = tok * 2 + 1;  g_inv[tok * 2 + 1] = p1;
}

// ---------------- fp16 GEMM, cp.async 3-stage, all-fp16 operands -------------
// CTA tile 128x128, BK=32, 3 stages x 20KB = 60KB smem (2 CTA/SM).
// MODE 0: g_h = relu(gather(xh) @ w1h^T + b1)      (K=DI,  NTOT=DH)
//         + converter CTAs (blockIdx.y >= MAXT) convert w2 -> w2h.
// MODE 1: g_contrib = (g_h @ w2h^T + b2) * gate_w  (K=DH,  NTOT=DOUT)
#define TS 40
#define ABUF_BYTES (128 * TS * 2)         // 10240
#define STAGE_BYTES (2 * ABUF_BYTES)      // 20480
#define NSTAGE 3
#define GEMM_SMEM (NSTAGE * STAGE_BYTES)  // 61440

template <int K, int NTOT, int MODE>
__global__ __launch_bounds__(256) void gemm_tc(const float* __restrict__ bias,
                                               const float4* __restrict__ w2f4) {
    if (MODE == 0 && blockIdx.y >= MAXT) {           // w2 fp32 -> fp16 converter
        int cid = (blockIdx.y - MAXT) * gridDim.x + blockIdx.x;   // 0..127
        size_t base = (size_t)cid * 256 + threadIdx.x;
        const size_t STRIDE = (size_t)(W2CY * 16) * 256;
        uint2* dst = (uint2*)g_w2h;
        #pragma unroll 4
        for (int i = 0; i < (NE * DOUT * DH / 4) / (W2CY * 16 * 256); ++i)
            dst[base + i * STRIDE] = cvt2h(w2f4[base + i * STRIDE]);
        return;
    }

    extern __shared__ __half smh[];
    __shared__ float bias_s[128];
    const int NC = K / 32;

    int e = g_tile_e[blockIdx.y];
    if (e < 0) return;
    int m0 = g_tile_m[blockIdx.y];
    int mEnd = g_off[e + 1];
    int n0 = blockIdx.x * 128;

    int tid = threadIdx.x, lane = tid & 31, wid = tid >> 5;
    int mw = (wid >> 2) * 64;
    int nw = (wid & 3) * 32;

    if (tid < 128) bias_s[tid] = bias[e * NTOT + n0 + tid];

    // ---- cp.async loader mapping: row = tid>>1, half-pair seg = (tid&1)*16
    int row = tid >> 1;
    int seg = (tid & 1) * 16;                 // halfs
    const __half* Wh = (MODE == 0) ? g_w1h : g_w2h;
    const __half* Ah = (MODE == 0) ? g_xh : g_h;
    int gRow = m0 + row;
    int cRow = (gRow < mEnd) ? gRow : m0;
    int aRowIdx = (MODE == 0) ? (g_perm[cRow] >> 1) : cRow;
    const __half* aSrc = Ah + (size_t)aRowIdx * K + seg;
    const __half* bSrc = Wh + (size_t)e * NTOT * K + (size_t)(n0 + row) * K + seg;

    uint32_t sb = (uint32_t)__cvta_generic_to_shared(smh);
    uint32_t rowOff = (uint32_t)(row * TS + seg) * 2;  // bytes within tile

    // ---- fragment addressing (same layout as R6)
    uint32_t aAddrBase = sb + (uint32_t)(((mw + (lane & 15)) * TS + (lane >> 4) * 8) * 2);
    int bg = lane >> 3;
    int nblk = bg >> 1, khalf = bg & 1;
    uint32_t bAddrBase = sb + (uint32_t)(ABUF_BYTES +
        ((nw + nblk * 8 + (lane & 7)) * TS + khalf * 8) * 2);

    float acc[4][4][4];
    #pragma unroll
    for (int mi = 0; mi < 4; ++mi)
        #pragma unroll
        for (int ni = 0; ni < 4; ++ni)
            #pragma unroll
            for (int j = 0; j < 4; ++j) acc[mi][ni][j] = 0.f;

    // ---- prologue: issue first NSTAGE-1 stages
    #pragma unroll
    for (int s = 0; s < NSTAGE - 1; ++s) {
        uint32_t base = sb + s * STAGE_BYTES;
        cp16(base + rowOff, aSrc + s * 32);
        cp16(base + rowOff + 16, aSrc + s * 32 + 8);
        cp16(base + ABUF_BYTES + rowOff, bSrc + s * 32);
        cp16(base + ABUF_BYTES + rowOff + 16, bSrc + s * 32 + 8);
        cp_commit();
    }

    for (int s = 0; s < NC; ++s) {
        if (s < NC - 1) cp_wait<NSTAGE - 2>(); else cp_wait<0>();
        __syncthreads();

        int buf = s % NSTAGE;
        uint32_t aA = aAddrBase + buf * STAGE_BYTES;
        uint32_t bA = bAddrBase + buf * STAGE_BYTES;
        #pragma unroll
        for (int ks = 0; ks < 2; ++ks) {
            uint32_t af[4][4];
            #pragma unroll
            for (int mi = 0; mi < 4; ++mi)
                ldsm4(aA + mi * (16 * TS * 2) + ks * 32, af[mi]);
            uint32_t bfr[8];
            #pragma unroll
            for (int ni2 = 0; ni2 < 2; ++ni2)
                ldsm4(bA + ni2 * (16 * TS * 2) + ks * 32, &bfr[ni2 * 4]);
            #pragma unroll
            for (int mi = 0; mi < 4; ++mi)
                #pragma unroll
                for (int ni = 0; ni < 4; ++ni)
                    mma_f16(acc[mi][ni], af[mi], &bfr[ni * 2]);
        }

        int ns = s + NSTAGE - 1;
        if (ns < NC) {
            uint32_t base = sb + (ns % NSTAGE) * STAGE_BYTES;
            cp16(base + rowOff, aSrc + ns * 32);
            cp16(base + rowOff + 16, aSrc + ns * 32 + 8);
            cp16(base + ABUF_BYTES + rowOff, bSrc + ns * 32);
            cp16(base + ABUF_BYTES + rowOff + 16, bSrc + ns * 32 + 8);
            cp_commit();
        }
    }

    // ---- epilogue
    int r4 = lane >> 2, cc = (lane & 3) * 2;
    #pragma unroll
    for (int mi = 0; mi < 4; ++mi) {
        int row0 = m0 + mw + mi * 16 + r4;
        int row1 = row0 + 8;
        bool v0 = row0 < mEnd, v1 = row1 < mEnd;
        if (MODE == 0) {
            __half* C0 = g_h + (size_t)row0 * NTOT + n0;
            __half* C1 = g_h + (size_t)row1 * NTOT + n0;
            #pragma unroll
            for (int ni = 0; ni < 4; ++ni) {
                int col = nw + ni * 8 + cc;
                float bb0 = bias_s[col], bb1 = bias_s[col + 1];
                const float* d = acc[mi][ni];
                if (v0) {
                    __half2 h = __floats2half2_rn(fmaxf(d[0] + bb0, 0.f),
                                                  fmaxf(d[1] + bb1, 0.f));
                    *(__half2*)&C0[col] = h;
                }
                if (v1) {
                    __half2 h = __floats2half2_rn(fmaxf(d[2] + bb0, 0.f),
                                                  fmaxf(d[3] + bb1, 0.f));
                    *(__half2*)&C1[col] = h;
                }
            }
        } else {
            float w0 = 1.f, w1 = 1.f;
            if (v0) w0 = g_tw[g_perm[row0]];
            if (v1) w1 = g_tw[g_perm[row1]];
            float* C0 = g_contrib + (size_t)row0 * NTOT + n0;
            float* C1 = g_contrib + (size_t)row1 * NTOT + n0;
            #pragma unroll
            for (int ni = 0; ni < 4; ++ni) {
                int col = nw + ni * 8 + cc;
                float bb0 = bias_s[col], bb1 = bias_s[col + 1];
                const float* d = acc[mi][ni];
                if (v0) {
                    float2 o; o.x = (d[0] + bb0) * w0; o.y = (d[1] + bb1) * w0;
                    *(float2*)&C0[col] = o;
                }
                if (v1) {
                    float2 o; o.x = (d[2] + bb0) * w1; o.y = (d[3] + bb1) * w1;
                    *(float2*)&C1[col] = o;
                }
            }
        }
    }
}

// ---------------- combine (+ reset counters for next replay) ------------------
__global__ __launch_bounds__(256) void combine_kernel(float* __restrict__ out) {
    int idx = blockIdx.x * 256 + threadIdx.x;
    int tok = idx >> 8;
    int d4 = idx & 255;
    const float4* c0 = (const float4*)&g_contrib[(size_t)g_inv[tok * 2 + 0] * DOUT];
    const float4* c1 = (const float4*)&g_contrib[(size_t)g_inv[tok * 2 + 1] * DOUT];
    float4 a = c0[d4], b = c1[d4];
    float4 r;
    r.x = a.x + b.x; r.y = a.y + b.y; r.z = a.z + b.z; r.w = a.w + b.w;
    ((float4*)out)[idx] = r;
    if (blockIdx.x == 0 && threadIdx.x < NE) {       // counters start zeroed;
        g_counts[threadIdx.x] = 0;                   // re-zero for next replay
        g_cursor[threadIdx.x] = 0;
    }
}

// ---------------- launch -----------------------------------------------------
extern "C" void kernel_launch(void* const* d_in, const int* in_sizes, int n_in,
                              void* d_out, int out_size) {
    const float* x  = (const float*)d_in[0];
    const float* gw = (const float*)d_in[1];
    const float* w1 = (const float*)d_in[2];
    const float* b1 = (const float*)d_in[3];
    const float* w2 = (const float*)d_in[4];
    const float* b2 = (const float*)d_in[5];
    float* out = (float*)d_out;

    cudaFuncSetAttribute(gemm_tc<DI, DH, 0>,
                         cudaFuncAttributeMaxDynamicSharedMemorySize, GEMM_SMEM);
    cudaFuncSetAttribute(gemm_tc<DH, DOUT, 1>,
                         cudaFuncAttributeMaxDynamicSharedMemorySize, GEMM_SMEM);

    gate_kernel<<<NB / 4 + W1CB, 128>>>(x, gw, (const float4*)w1);
    prefix_kernel<<<1, 32>>>();
    scatter_kernel<<<NB / 256 + XCB, 256>>>((const float4*)x);
    gemm_tc<DI, DH, 0><<<dim3(DH / 128, MAXT + W2CY), 256, GEMM_SMEM>>>(b1, (const float4*)w2);
    gemm_tc<DH, DOUT, 1><<<dim3(DOUT / 128, MAXT), 256, GEMM_SMEM>>>(b2, nullptr);
    combine_kernel<<<NB * (DOUT / 4) / 256, 256>>>(out);
}